// round 8
// baseline (speedup 1.0000x reference)
#include <cuda_runtime.h>
#include <cuda_bf16.h>
#include <math.h>

#define ED 1536
#define BN 64
#define MT 128
#define NTH 256
#define NCH 24

// ---- smem byte offsets (from 1KB-aligned base) ----
#define O_WB(b)  ((b) * 16384)     // W chunk double buffer: hi @+0 (8KB), lo @+8192
#define O_HH     32768             // H hi: 128 rows x 128B = 16KB
#define O_HL     49152             // H lo
#define O_BU     65536             // b_up 6KB
#define O_S1     71680
#define O_S2     71936
#define O_INV    72192             // 128 floats
#define SMEM_REQ (72704 + 1024)

__device__ __nv_bfloat16 g_wdh[BN * ED];   // [24][64 n][64 k]
__device__ __nv_bfloat16 g_wdl[BN * ED];
__device__ __nv_bfloat16 g_wuh[ED * BN];   // [24][64 d][64 k]
__device__ __nv_bfloat16 g_wul[ED * BN];
__device__ float g_S1[BN], g_S2[BN];

// 128B rows, 8 units of 16B, XOR swizzle
__device__ __forceinline__ unsigned SWB(unsigned r, unsigned u) {
    return r * 128 + (((u ^ r) & 7) * 16);
}

__device__ __forceinline__ void ldsm4(unsigned* r, unsigned a) {
    asm volatile("ldmatrix.sync.aligned.m8n8.x4.shared.b16 {%0,%1,%2,%3}, [%4];"
                 : "=r"(r[0]), "=r"(r[1]), "=r"(r[2]), "=r"(r[3]) : "r"(a));
}
__device__ __forceinline__ void mma_bf(float* c, const unsigned* a, const unsigned* b) {
    asm volatile("mma.sync.aligned.m16n8k16.row.col.f32.bf16.bf16.f32 "
                 "{%0,%1,%2,%3},{%4,%5,%6,%7},{%8,%9},{%0,%1,%2,%3};"
                 : "+f"(c[0]), "+f"(c[1]), "+f"(c[2]), "+f"(c[3])
                 : "r"(a[0]), "r"(a[1]), "r"(a[2]), "r"(a[3]), "r"(b[0]), "r"(b[1]));
}
__device__ __forceinline__ void cp16(unsigned dst, const void* src) {
    asm volatile("cp.async.cg.shared.global [%0], [%1], 16;" :: "r"(dst), "l"(src));
}
#define CP_COMMIT() asm volatile("cp.async.commit_group;" ::: "memory")
#define CP_WAIT0()  asm volatile("cp.async.wait_group 0;" ::: "memory")

__device__ __forceinline__ void split2(float a, float b, unsigned& h, unsigned& l) {
    __nv_bfloat16 ha = __float2bfloat16_rn(a), hb = __float2bfloat16_rn(b);
    float ra = a - __bfloat162float(ha), rb = b - __bfloat162float(hb);
    __nv_bfloat16 la = __float2bfloat16_rn(ra), lb = __float2bfloat16_rn(rb);
    h = (unsigned)__bfloat16_as_ushort(ha) | ((unsigned)__bfloat16_as_ushort(hb) << 16);
    l = (unsigned)__bfloat16_as_ushort(la) | ((unsigned)__bfloat16_as_ushort(lb) << 16);
}
__device__ __forceinline__ float gelu_exact(float t) {
    return 0.5f * t * (1.f + erff(t * 0.70710678118654752f));
}

// ---------- merged prep: blocks 0..63 -> w_down row; 64..87 -> w_up chunk ----------
__global__ void prep_all(const float* __restrict__ w_down, const float* __restrict__ b_down,
                         const float* __restrict__ gamma,  const float* __restrict__ beta,
                         const float* __restrict__ w_up) {
    int tid = threadIdx.x;
    if (blockIdx.x < 64) {
        int b = blockIdx.x;
        float s1 = 0.f, s2 = 0.f;
        for (int k = tid; k < ED; k += 256) {
            float w = w_down[b * ED + k];
            float wg = w * gamma[k];
            s1 += wg; s2 += beta[k] * w;
            __nv_bfloat16 hi = __float2bfloat16_rn(wg);
            __nv_bfloat16 lo = __float2bfloat16_rn(wg - __bfloat162float(hi));
            int idx = (k >> 6) * 4096 + b * 64 + (k & 63);
            g_wdh[idx] = hi; g_wdl[idx] = lo;
        }
        __shared__ float r1[256], r2[256];
        r1[tid] = s1; r2[tid] = s2; __syncthreads();
        for (int s = 128; s > 0; s >>= 1) {
            if (tid < s) { r1[tid] += r1[tid + s]; r2[tid] += r2[tid + s]; }
            __syncthreads();
        }
        if (tid == 0) { g_S1[b] = r1[0]; g_S2[b] = r2[0] + b_down[b]; }
    } else {
        int c = blockIdx.x - 64;
        for (int i = tid; i < 4096; i += 256) {
            int d = i >> 6, k = i & 63;
            float w = w_up[(c * 64 + d) * BN + k];
            __nv_bfloat16 hi = __float2bfloat16_rn(w);
            __nv_bfloat16 lo = __float2bfloat16_rn(w - __bfloat162float(hi));
            g_wuh[c * 4096 + i] = hi; g_wul[c * 4096 + i] = lo;
        }
    }
}

// ---------- main ----------
__global__ void __launch_bounds__(NTH, 2)
peft_mma(const float* __restrict__ x, const float* __restrict__ bup, float* __restrict__ out) {
    extern __shared__ char smraw[];
    unsigned rawa = (unsigned)__cvta_generic_to_shared(smraw);
    unsigned sa = (rawa + 1023) & ~1023u;
    char* sb = smraw + (sa - rawa);

    const int tid = threadIdx.x, warp = tid >> 5, lane = tid & 31;
    const int m = warp;                  // 8 m-tiles of 16 rows
    const long row0 = (long)blockIdx.x * MT;
    const int rl = lane >> 2;            // row-in-tile (0..7)
    const int cb = (lane & 3) * 2;       // col pair base

    float* BU  = (float*)(sb + O_BU);
    float* S1s = (float*)(sb + O_S1);
    float* S2s = (float*)(sb + O_S2);

    for (int i = tid; i < ED; i += NTH) BU[i] = bup[i];
    if (tid < BN) { S1s[tid] = g_S1[tid]; S2s[tid] = g_S2[tid]; }

    const long rA = row0 + m * 16 + rl;
    const long rB = rA + 8;
    const float* xA = x + rA * ED;
    const float* xB = x + rB * ED;

    // ---- prologue: stage Wd chunk 0, prefetch x chunk 0 into regs ----
    {
        #pragma unroll
        for (int s = 0; s < 2; ++s) {
            int i = tid * 2 + s, n = i >> 3, u = i & 7;
            cp16(sa + O_WB(0) + SWB(n, u),        g_wdh + n * 64 + u * 8);
            cp16(sa + O_WB(0) + 8192 + SWB(n, u), g_wdl + n * 64 + u * 8);
        }
        CP_COMMIT();
    }
    float2 p0[4], p1[4], p2[4], p3[4];
    #pragma unroll
    for (int kt = 0; kt < 4; ++kt) {
        int col = kt * 16 + cb;
        p0[kt] = *(const float2*)(xA + col);
        p1[kt] = *(const float2*)(xB + col);
        p2[kt] = *(const float2*)(xA + col + 8);
        p3[kt] = *(const float2*)(xB + col + 8);
    }

    // ================= GEMM1: H[128,64] = X * (gamma*Wd)^T =================
    float C1[8][4];
    #pragma unroll
    for (int nt = 0; nt < 8; ++nt)
        #pragma unroll
        for (int i = 0; i < 4; ++i) C1[nt][i] = 0.f;

    float sumA = 0.f, sqA = 0.f, sumB = 0.f, sqB = 0.f;

    for (int c = 0; c < NCH; ++c) {
        CP_WAIT0();
        __syncthreads();
        if (c < NCH - 1) {
            #pragma unroll
            for (int s = 0; s < 2; ++s) {
                int i = tid * 2 + s, n = i >> 3, u = i & 7;
                cp16(sa + O_WB((c + 1) & 1) + SWB(n, u),        g_wdh + (c + 1) * 4096 + n * 64 + u * 8);
                cp16(sa + O_WB((c + 1) & 1) + 8192 + SWB(n, u), g_wdl + (c + 1) * 4096 + n * 64 + u * 8);
            }
            CP_COMMIT();
        }
        // convert prefetched x -> A fragments (regs) + LN stats
        unsigned ah[4][4], al[4][4];
        #pragma unroll
        for (int kt = 0; kt < 4; ++kt) {
            sumA += p0[kt].x + p0[kt].y + p2[kt].x + p2[kt].y;
            sqA  += p0[kt].x*p0[kt].x + p0[kt].y*p0[kt].y + p2[kt].x*p2[kt].x + p2[kt].y*p2[kt].y;
            sumB += p1[kt].x + p1[kt].y + p3[kt].x + p3[kt].y;
            sqB  += p1[kt].x*p1[kt].x + p1[kt].y*p1[kt].y + p3[kt].x*p3[kt].x + p3[kt].y*p3[kt].y;
            split2(p0[kt].x, p0[kt].y, ah[kt][0], al[kt][0]);
            split2(p1[kt].x, p1[kt].y, ah[kt][1], al[kt][1]);
            split2(p2[kt].x, p2[kt].y, ah[kt][2], al[kt][2]);
            split2(p3[kt].x, p3[kt].y, ah[kt][3], al[kt][3]);
        }
        // prefetch x chunk c+1
        if (c < NCH - 1) {
            #pragma unroll
            for (int kt = 0; kt < 4; ++kt) {
                int col = (c + 1) * 64 + kt * 16 + cb;
                p0[kt] = *(const float2*)(xA + col);
                p1[kt] = *(const float2*)(xB + col);
                p2[kt] = *(const float2*)(xA + col + 8);
                p3[kt] = *(const float2*)(xB + col + 8);
            }
        }
        // MMA block
        unsigned wb = sa + O_WB(c & 1);
        #pragma unroll
        for (int nt = 0; nt < 8; ++nt) {
            unsigned bh[2][4], bl[2][4];
            unsigned rowB_ = nt * 8 + (lane & 7);
            #pragma unroll
            for (int kp = 0; kp < 2; ++kp) {
                unsigned uB = 4 * kp + (lane >> 3);
                ldsm4(bh[kp], wb + SWB(rowB_, uB));
                ldsm4(bl[kp], wb + 8192 + SWB(rowB_, uB));
            }
            #pragma unroll
            for (int kk = 0; kk < 4; ++kk) {
                const unsigned* bhp = &bh[kk >> 1][(kk & 1) * 2];
                const unsigned* blp = &bl[kk >> 1][(kk & 1) * 2];
                mma_bf(C1[nt], ah[kk], bhp);
                mma_bf(C1[nt], al[kk], bhp);
                mma_bf(C1[nt], ah[kk], blp);
            }
        }
    }

    // ---- LN stats reduce (4 lanes per row group) ----
    #pragma unroll
    for (int o = 1; o < 4; o <<= 1) {
        sumA += __shfl_xor_sync(0xFFFFFFFFu, sumA, o);
        sqA  += __shfl_xor_sync(0xFFFFFFFFu, sqA,  o);
        sumB += __shfl_xor_sync(0xFFFFFFFFu, sumB, o);
        sqB  += __shfl_xor_sync(0xFFFFFFFFu, sqB,  o);
    }
    const float meanA = sumA * (1.f / ED);
    const float rstdA = rsqrtf(sqA * (1.f / ED) - meanA * meanA + 1e-5f);
    const float meanB = sumB * (1.f / ED);
    const float rstdB = rsqrtf(sqB * (1.f / ED) - meanB * meanB + 1e-5f);

    // ---- LN finalize + GELU on C1 frags, store bf16 hi/lo -> HH/HL ----
    {
        int rowA_ = m * 16 + rl, rowB_ = rowA_ + 8;
        #pragma unroll
        for (int nt = 0; nt < 8; ++nt) {
            int c0 = nt * 8 + cb;
            float s1a = S1s[c0], s1b = S1s[c0 + 1];
            float s2a = S2s[c0], s2b = S2s[c0 + 1];
            float tA0 = rstdA * C1[nt][0] - rstdA * meanA * s1a + s2a;
            float tA1 = rstdA * C1[nt][1] - rstdA * meanA * s1b + s2b;
            float tB0 = rstdB * C1[nt][2] - rstdB * meanB * s1a + s2a;
            float tB1 = rstdB * C1[nt][3] - rstdB * meanB * s1b + s2b;
            unsigned h, l;
            split2(gelu_exact(tA0), gelu_exact(tA1), h, l);
            unsigned offA = SWB(rowA_, nt) + cb * 2;
            *(unsigned*)(sb + O_HH + offA) = h;
            *(unsigned*)(sb + O_HL + offA) = l;
            split2(gelu_exact(tB0), gelu_exact(tB1), h, l);
            unsigned offB = SWB(rowB_, nt) + cb * 2;
            *(unsigned*)(sb + O_HH + offB) = h;
            *(unsigned*)(sb + O_HL + offB) = l;
        }
    }
    __syncthreads();

    // ================= GEMM2: out = H * Wu^T + b_up + x =================
    unsigned Ah[4][4], Al[4][4];
    {
        unsigned rowA_ = m * 16 + (lane & 15);
        #pragma unroll
        for (int kk = 0; kk < 4; ++kk) {
            unsigned uA = 2 * kk + (lane >> 4);
            ldsm4(Ah[kk], sa + O_HH + SWB(rowA_, uA));
            ldsm4(Al[kk], sa + O_HL + SWB(rowA_, uA));
        }
    }
    {
        #pragma unroll
        for (int s = 0; s < 2; ++s) {
            int i = tid * 2 + s, d = i >> 3, u = i & 7;
            cp16(sa + O_WB(0) + SWB(d, u),        g_wuh + d * 64 + u * 8);
            cp16(sa + O_WB(0) + 8192 + SWB(d, u), g_wul + d * 64 + u * 8);
        }
        CP_COMMIT();
    }

    float na = 0.f, nb = 0.f;
    for (int c = 0; c < NCH; ++c) {
        CP_WAIT0();
        __syncthreads();
        if (c < NCH - 1) {
            #pragma unroll
            for (int s = 0; s < 2; ++s) {
                int i = tid * 2 + s, d = i >> 3, u = i & 7;
                cp16(sa + O_WB((c + 1) & 1) + SWB(d, u),        g_wuh + (c + 1) * 4096 + d * 64 + u * 8);
                cp16(sa + O_WB((c + 1) & 1) + 8192 + SWB(d, u), g_wul + (c + 1) * 4096 + d * 64 + u * 8);
            }
            CP_COMMIT();
        }
        // residual prefetch
        float2 fA[8], fB[8];
        #pragma unroll
        for (int nt = 0; nt < 8; ++nt) {
            int col = c * 64 + nt * 8 + cb;
            fA[nt] = *(const float2*)(xA + col);
            fB[nt] = *(const float2*)(xB + col);
        }
        unsigned wb = sa + O_WB(c & 1);
        #pragma unroll
        for (int nt = 0; nt < 8; ++nt) {
            float C2[4] = {0.f, 0.f, 0.f, 0.f};
            unsigned bh[2][4], bl[2][4];
            unsigned rowB_ = nt * 8 + (lane & 7);
            #pragma unroll
            for (int kp = 0; kp < 2; ++kp) {
                unsigned uB = 4 * kp + (lane >> 3);
                ldsm4(bh[kp], wb + SWB(rowB_, uB));
                ldsm4(bl[kp], wb + 8192 + SWB(rowB_, uB));
            }
            #pragma unroll
            for (int kk = 0; kk < 4; ++kk) {
                const unsigned* bhp = &bh[kk >> 1][(kk & 1) * 2];
                const unsigned* blp = &bl[kk >> 1][(kk & 1) * 2];
                mma_bf(C2, Ah[kk], bhp);
                mma_bf(C2, Al[kk], bhp);
                mma_bf(C2, Ah[kk], blp);
            }
            int col = c * 64 + nt * 8 + cb;
            float v0 = C2[0] + fA[nt].x + BU[col];
            float v1 = C2[1] + fA[nt].y + BU[col + 1];
            na += v0 * v0 + v1 * v1;
            *(float2*)(out + rA * ED + col) = make_float2(v0, v1);
            float v2 = C2[2] + fB[nt].x + BU[col];
            float v3 = C2[3] + fB[nt].y + BU[col + 1];
            nb += v2 * v2 + v3 * v3;
            *(float2*)(out + rB * ED + col) = make_float2(v2, v3);
        }
    }

    // ---- row norms -> INV ----
    #pragma unroll
    for (int o = 1; o < 4; o <<= 1) {
        na += __shfl_xor_sync(0xFFFFFFFFu, na, o);
        nb += __shfl_xor_sync(0xFFFFFFFFu, nb, o);
    }
    if ((lane & 3) == 0) {
        ((float*)(sb + O_INV))[m * 16 + rl]     = 1.f / fmaxf(sqrtf(na), 1e-12f);
        ((float*)(sb + O_INV))[m * 16 + rl + 8] = 1.f / fmaxf(sqrtf(nb), 1e-12f);
    }
    __syncthreads();

    // ---- rescale (L2-hot re-read of this CTA's output) ----
    {
        int r = tid >> 1, h = tid & 1;
        float sc = ((float*)(sb + O_INV))[r];
        float4* op = (float4*)(out + (row0 + r) * ED) + h * 192;
        #pragma unroll 8
        for (int j = 0; j < 192; ++j) {
            float4 v = op[j];
            v.x *= sc; v.y *= sc; v.z *= sc; v.w *= sc;
            op[j] = v;
        }
    }
}

extern "C" void kernel_launch(void* const* d_in, const int* in_sizes, int n_in,
                              void* d_out, int out_size) {
    const float* x      = (const float*)d_in[0];
    const float* w_down = (const float*)d_in[1];
    const float* b_down = (const float*)d_in[2];
    const float* w_up   = (const float*)d_in[3];
    const float* b_up   = (const float*)d_in[4];
    const float* gamma  = (const float*)d_in[5];
    const float* beta   = (const float*)d_in[6];
    float* out = (float*)d_out;

    const int n_rows = in_sizes[0] / ED;   // 32768

    cudaFuncSetAttribute(peft_mma, cudaFuncAttributeMaxDynamicSharedMemorySize, SMEM_REQ);

    prep_all<<<88, 256>>>(w_down, b_down, gamma, beta, w_up);
    peft_mma<<<n_rows / MT, NTH, SMEM_REQ>>>(x, b_up, out);
}

// round 9
// speedup vs baseline: 1.3879x; 1.3879x over previous
#include <cuda_runtime.h>
#include <cuda_bf16.h>
#include <math.h>

#define ED 1536
#define BN 64
#define MT 64
#define NTH 256
#define NCH 24

// ---- smem byte offsets (from 1KB-aligned base) ----
#define O_XB(b)  ((b) * 16384)            // X chunk: hi @+0 (8KB), lo @+8192
#define O_WB(b)  (32768 + (b) * 16384)    // W chunk: hi @+0, lo @+8192 (GEMM2 uses hi only)
#define O_HH     65536
#define O_HRAW   0                        // overlay on XB region (64 x 66 fp32)
#define O_BU     81920
#define O_S1     88064
#define O_S2     88320
#define O_MS     88576
#define O_RS     88832
#define O_NRM    89088                    // 64 x 5 fp32
#define O_INV    91392
#define SMEM_REQ (91648 + 1024)

__device__ __nv_bfloat16 g_wdh[BN * ED];   // [24][64 n][64 k]
__device__ __nv_bfloat16 g_wdl[BN * ED];
__device__ __nv_bfloat16 g_wuh[ED * BN];   // [24][64 d][64 k]
__device__ float g_S1[BN], g_S2[BN];

// 128B rows, 8 units of 16B, XOR swizzle
__device__ __forceinline__ unsigned SWB(unsigned r, unsigned u) {
    return r * 128 + (((u ^ r) & 7) * 16);
}

__device__ __forceinline__ void ldsm4(unsigned* r, unsigned a) {
    asm volatile("ldmatrix.sync.aligned.m8n8.x4.shared.b16 {%0,%1,%2,%3}, [%4];"
                 : "=r"(r[0]), "=r"(r[1]), "=r"(r[2]), "=r"(r[3]) : "r"(a));
}
__device__ __forceinline__ void mma_bf(float* c, const unsigned* a, const unsigned* b) {
    asm volatile("mma.sync.aligned.m16n8k16.row.col.f32.bf16.bf16.f32 "
                 "{%0,%1,%2,%3},{%4,%5,%6,%7},{%8,%9},{%0,%1,%2,%3};"
                 : "+f"(c[0]), "+f"(c[1]), "+f"(c[2]), "+f"(c[3])
                 : "r"(a[0]), "r"(a[1]), "r"(a[2]), "r"(a[3]), "r"(b[0]), "r"(b[1]));
}
__device__ __forceinline__ void cp16(unsigned dst, const void* src) {
    asm volatile("cp.async.cg.shared.global [%0], [%1], 16;" :: "r"(dst), "l"(src));
}
#define CP_COMMIT() asm volatile("cp.async.commit_group;" ::: "memory")
#define CP_WAIT0()  asm volatile("cp.async.wait_group 0;" ::: "memory")

__device__ __forceinline__ void split2(float a, float b, unsigned& h, unsigned& l) {
    __nv_bfloat16 ha = __float2bfloat16_rn(a), hb = __float2bfloat16_rn(b);
    float ra = a - __bfloat162float(ha), rb = b - __bfloat162float(hb);
    __nv_bfloat16 la = __float2bfloat16_rn(ra), lb = __float2bfloat16_rn(rb);
    h = (unsigned)__bfloat16_as_ushort(ha) | ((unsigned)__bfloat16_as_ushort(hb) << 16);
    l = (unsigned)__bfloat16_as_ushort(la) | ((unsigned)__bfloat16_as_ushort(lb) << 16);
}
__device__ __forceinline__ unsigned pack_bf(float a, float b) {
    __nv_bfloat16 ha = __float2bfloat16_rn(a), hb = __float2bfloat16_rn(b);
    return (unsigned)__bfloat16_as_ushort(ha) | ((unsigned)__bfloat16_as_ushort(hb) << 16);
}
__device__ __forceinline__ float gelu_exact(float t) {
    return 0.5f * t * (1.f + erff(t * 0.70710678118654752f));
}

// ---------- merged prep: blocks 0..63 -> w_down row; 64..87 -> w_up chunk ----------
__global__ void prep_all(const float* __restrict__ w_down, const float* __restrict__ b_down,
                         const float* __restrict__ gamma,  const float* __restrict__ beta,
                         const float* __restrict__ w_up) {
    int tid = threadIdx.x;
    if (blockIdx.x < 64) {
        int b = blockIdx.x;
        float s1 = 0.f, s2 = 0.f;
        for (int k = tid; k < ED; k += 256) {
            float w = w_down[b * ED + k];
            float wg = w * gamma[k];
            s1 += wg; s2 += beta[k] * w;
            __nv_bfloat16 hi = __float2bfloat16_rn(wg);
            __nv_bfloat16 lo = __float2bfloat16_rn(wg - __bfloat162float(hi));
            int idx = (k >> 6) * 4096 + b * 64 + (k & 63);
            g_wdh[idx] = hi; g_wdl[idx] = lo;
        }
        __shared__ float r1[256], r2[256];
        r1[tid] = s1; r2[tid] = s2; __syncthreads();
        for (int s = 128; s > 0; s >>= 1) {
            if (tid < s) { r1[tid] += r1[tid + s]; r2[tid] += r2[tid + s]; }
            __syncthreads();
        }
        if (tid == 0) { g_S1[b] = r1[0]; g_S2[b] = r2[0] + b_down[b]; }
    } else {
        int c = blockIdx.x - 64;
        for (int i = tid; i < 4096; i += 256) {
            int d = i >> 6, k = i & 63;
            g_wuh[c * 4096 + i] = __float2bfloat16_rn(w_up[(c * 64 + d) * BN + k]);
        }
    }
}

// ---------- main ----------
__global__ void __launch_bounds__(NTH, 2)
peft_mma(const float* __restrict__ x, const float* __restrict__ bup, float* __restrict__ out) {
    extern __shared__ char smraw[];
    unsigned rawa = (unsigned)__cvta_generic_to_shared(smraw);
    unsigned sa = (rawa + 1023) & ~1023u;
    char* sb = smraw + (sa - rawa);

    const int tid = threadIdx.x, warp = tid >> 5, lane = tid & 31;
    const int m = warp & 3, nh = warp >> 2;   // GEMM1: 4 m-tiles x 2 n-halves
    const long row0 = (long)blockIdx.x * MT;
    const int cr = tid >> 2, cs = tid & 3;    // conversion row / quarter
    const int cb = (lane & 3) * 2;            // col pair base

    float* BU  = (float*)(sb + O_BU);
    float* S1s = (float*)(sb + O_S1);
    float* S2s = (float*)(sb + O_S2);

    for (int i = tid; i < ED; i += NTH) BU[i] = bup[i];
    if (tid < BN) { S1s[tid] = g_S1[tid]; S2s[tid] = g_S2[tid]; }

    float sum = 0.f, sq = 0.f;

    // ---- prologue: stage Wd chunk 0 + convert X chunk 0 ----
    {
        #pragma unroll
        for (int s = 0; s < 2; ++s) {
            int i = tid * 2 + s, n = i >> 3, u = i & 7;
            cp16(sa + O_WB(0) + SWB(n, u),        g_wdh + n * 64 + u * 8);
            cp16(sa + O_WB(0) + 8192 + SWB(n, u), g_wdl + n * 64 + u * 8);
        }
        CP_COMMIT();
    }
    {
        const float* xp = x + (row0 + cr) * ED;
        char* xb = sb + O_XB(0);
        #pragma unroll
        for (int g = 0; g < 2; ++g) {
            float4 v0 = *(const float4*)(xp + cs * 16 + g * 8);
            float4 v1 = *(const float4*)(xp + cs * 16 + g * 8 + 4);
            sum += v0.x + v0.y + v0.z + v0.w + v1.x + v1.y + v1.z + v1.w;
            sq  += v0.x*v0.x + v0.y*v0.y + v0.z*v0.z + v0.w*v0.w
                 + v1.x*v1.x + v1.y*v1.y + v1.z*v1.z + v1.w*v1.w;
            unsigned h0,l0,h1,l1,h2,l2,h3,l3;
            split2(v0.x, v0.y, h0, l0); split2(v0.z, v0.w, h1, l1);
            split2(v1.x, v1.y, h2, l2); split2(v1.z, v1.w, h3, l3);
            unsigned off = SWB(cr, 2 * cs + g);
            *(uint4*)(xb + off)        = make_uint4(h0, h1, h2, h3);
            *(uint4*)(xb + 8192 + off) = make_uint4(l0, l1, l2, l3);
        }
    }

    // ================= GEMM1: H[64,64] = X * (gamma*Wd)^T (3-term) =================
    float C1[4][4];
    #pragma unroll
    for (int nt = 0; nt < 4; ++nt)
        #pragma unroll
        for (int i = 0; i < 4; ++i) C1[nt][i] = 0.f;

    float4 pf0, pf1, pf2, pf3;
    for (int c = 0; c < NCH; ++c) {
        CP_WAIT0();
        __syncthreads();
        if (c < NCH - 1) {
            #pragma unroll
            for (int s = 0; s < 2; ++s) {
                int i = tid * 2 + s, n = i >> 3, u = i & 7;
                cp16(sa + O_WB((c + 1) & 1) + SWB(n, u),        g_wdh + (c + 1) * 4096 + n * 64 + u * 8);
                cp16(sa + O_WB((c + 1) & 1) + 8192 + SWB(n, u), g_wdl + (c + 1) * 4096 + n * 64 + u * 8);
            }
            CP_COMMIT();
            const float* xp = x + (row0 + cr) * ED + (c + 1) * 64 + cs * 16;
            pf0 = *(const float4*)(xp);
            pf1 = *(const float4*)(xp + 4);
            pf2 = *(const float4*)(xp + 8);
            pf3 = *(const float4*)(xp + 12);
        }
        unsigned xb = sa + O_XB(c & 1);
        unsigned wb = sa + O_WB(c & 1);
        const unsigned rowA = m * 16 + (lane & 15);
        #pragma unroll
        for (int kp = 0; kp < 2; ++kp) {
            unsigned ah0[4], al0[4], ah1[4], al1[4];
            unsigned uA0 = 4 * kp + (lane >> 4), uA1 = uA0 + 2;
            ldsm4(ah0, xb + SWB(rowA, uA0));
            ldsm4(al0, xb + 8192 + SWB(rowA, uA0));
            ldsm4(ah1, xb + SWB(rowA, uA1));
            ldsm4(al1, xb + 8192 + SWB(rowA, uA1));
            #pragma unroll
            for (int nt = 0; nt < 4; ++nt) {
                unsigned bh[4], bl[4];
                unsigned rowB = nh * 32 + nt * 8 + (lane & 7);
                unsigned uB = 4 * kp + (lane >> 3);
                ldsm4(bh, wb + SWB(rowB, uB));
                ldsm4(bl, wb + 8192 + SWB(rowB, uB));
                float* Cp = C1[nt];
                mma_bf(Cp, ah0, bh);     mma_bf(Cp, al0, bh);     mma_bf(Cp, ah0, bl);
                mma_bf(Cp, ah1, bh + 2); mma_bf(Cp, al1, bh + 2); mma_bf(Cp, ah1, bl + 2);
            }
        }
        if (c < NCH - 1) {
            char* xcb = sb + O_XB((c + 1) & 1);
            float4 vv[4] = {pf0, pf1, pf2, pf3};
            #pragma unroll
            for (int g = 0; g < 2; ++g) {
                float4 v0 = vv[g * 2], v1 = vv[g * 2 + 1];
                sum += v0.x + v0.y + v0.z + v0.w + v1.x + v1.y + v1.z + v1.w;
                sq  += v0.x*v0.x + v0.y*v0.y + v0.z*v0.z + v0.w*v0.w
                     + v1.x*v1.x + v1.y*v1.y + v1.z*v1.z + v1.w*v1.w;
                unsigned h0,l0,h1,l1,h2,l2,h3,l3;
                split2(v0.x, v0.y, h0, l0); split2(v0.z, v0.w, h1, l1);
                split2(v1.x, v1.y, h2, l2); split2(v1.z, v1.w, h3, l3);
                unsigned off = SWB(cr, 2 * cs + g);
                *(uint4*)(xcb + off)        = make_uint4(h0, h1, h2, h3);
                *(uint4*)(xcb + 8192 + off) = make_uint4(l0, l1, l2, l3);
            }
        }
    }

    // ---- LN stats: 4 lanes per row ----
    #pragma unroll
    for (int o = 1; o < 4; o <<= 1) {
        sum += __shfl_xor_sync(0xFFFFFFFFu, sum, o);
        sq  += __shfl_xor_sync(0xFFFFFFFFu, sq,  o);
    }
    if (cs == 0) {
        float mean = sum * (1.f / ED);
        ((float*)(sb + O_MS))[cr] = mean;
        ((float*)(sb + O_RS))[cr] = rsqrtf(sq * (1.f / ED) - mean * mean + 1e-5f);
    }
    __syncthreads();

    // ---- write C1 frags -> HRAW (overlaid on XB) ----
    {
        float* Hr = (float*)(sb + O_HRAW);
        #pragma unroll
        for (int nt = 0; nt < 4; ++nt)
            #pragma unroll
            for (int h = 0; h < 2; ++h) {
                int row = m * 16 + (lane >> 2) + h * 8;
                int col = nh * 32 + nt * 8 + 2 * (lane & 3);
                *(float2*)(Hr + row * 66 + col) = make_float2(C1[nt][h * 2], C1[nt][h * 2 + 1]);
            }
    }
    __syncthreads();

    // ---- LN finalize + GELU -> HH (bf16 hi only) ----
    {
        const float* Hr = (const float*)(sb + O_HRAW);
        float mean = ((float*)(sb + O_MS))[cr], rstd = ((float*)(sb + O_RS))[cr];
        #pragma unroll
        for (int g = 0; g < 2; ++g) {
            unsigned hw[4];
            #pragma unroll
            for (int p = 0; p < 4; ++p) {
                int c0 = cs * 16 + g * 8 + p * 2;
                float v0 = Hr[cr * 66 + c0], v1 = Hr[cr * 66 + c0 + 1];
                float t0 = rstd * v0 - rstd * mean * S1s[c0]     + S2s[c0];
                float t1 = rstd * v1 - rstd * mean * S1s[c0 + 1] + S2s[c0 + 1];
                hw[p] = pack_bf(gelu_exact(t0), gelu_exact(t1));
            }
            unsigned off = SWB(cr, 2 * cs + g);
            *(uint4*)(sb + O_HH + off) = make_uint4(hw[0], hw[1], hw[2], hw[3]);
        }
    }
    __syncthreads();

    // ================= GEMM2 (single-term bf16): out = H * Wu^T + b_up + x =================
    // warp grid: 2 m-halves (32 rows) x 4 d-quarters (16 cols per 64-chunk)
    const int md = warp & 1;
    const int dq = warp >> 1;
    unsigned Ah[2][4][4];
    {
        #pragma unroll
        for (int mt = 0; mt < 2; ++mt) {
            unsigned rowA_ = md * 32 + mt * 16 + (lane & 15);
            #pragma unroll
            for (int kk = 0; kk < 4; ++kk) {
                unsigned uA = 2 * kk + (lane >> 4);
                ldsm4(Ah[mt][kk], sa + O_HH + SWB(rowA_, uA));
            }
        }
    }
    {
        #pragma unroll
        for (int s = 0; s < 2; ++s) {
            int i = tid * 2 + s, d = i >> 3, u = i & 7;
            cp16(sa + O_WB(0) + SWB(d, u), g_wuh + d * 64 + u * 8);
        }
        CP_COMMIT();
    }

    const long rA0 = row0 + md * 32 + (lane >> 2);       // mt=0 rows
    const long rA1 = rA0 + 16;                            // mt=1 rows
    float na[2] = {0.f, 0.f}, nb[2] = {0.f, 0.f};
    for (int c = 0; c < NCH; ++c) {
        CP_WAIT0();
        __syncthreads();
        if (c < NCH - 1) {
            #pragma unroll
            for (int s = 0; s < 2; ++s) {
                int i = tid * 2 + s, d = i >> 3, u = i & 7;
                cp16(sa + O_WB((c + 1) & 1) + SWB(d, u), g_wuh + (c + 1) * 4096 + d * 64 + u * 8);
            }
            CP_COMMIT();
        }
        // residual prefetch: [mt][half][nt]
        float2 fr[2][2][2];
        #pragma unroll
        for (int nt = 0; nt < 2; ++nt) {
            int col = c * 64 + dq * 16 + nt * 8 + cb;
            fr[0][0][nt] = *(const float2*)(x + rA0 * ED + col);
            fr[0][1][nt] = *(const float2*)(x + (rA0 + 8) * ED + col);
            fr[1][0][nt] = *(const float2*)(x + rA1 * ED + col);
            fr[1][1][nt] = *(const float2*)(x + (rA1 + 8) * ED + col);
        }
        unsigned wb = sa + O_WB(c & 1);
        unsigned bh[2][4];
        {
            unsigned rowB_ = dq * 16 + (lane & 7) + ((lane >> 4) << 3); // 16 rows via lane>>4? no:
        }
        // B frags: rows dq*16 + nt*8, k 0..63
        #pragma unroll
        for (int nt = 0; nt < 2; ++nt) {
            unsigned rowB_ = dq * 16 + nt * 8 + (lane & 7);
            #pragma unroll
            for (int kp = 0; kp < 2; ++kp) {
                unsigned uB = 4 * kp + (lane >> 3);
                ldsm4(bh[kp], wb + SWB(rowB_, uB));
            }
            #pragma unroll
            for (int mt = 0; mt < 2; ++mt) {
                float C2[4] = {0.f, 0.f, 0.f, 0.f};
                #pragma unroll
                for (int kk = 0; kk < 4; ++kk)
                    mma_bf(C2, Ah[mt][kk], &bh[kk >> 1][(kk & 1) * 2]);
                int col = c * 64 + dq * 16 + nt * 8 + cb;
                long r0_ = (mt ? rA1 : rA0);
                float v0 = C2[0] + fr[mt][0][nt].x + BU[col];
                float v1 = C2[1] + fr[mt][0][nt].y + BU[col + 1];
                na[mt] += v0 * v0 + v1 * v1;
                *(float2*)(out + r0_ * ED + col) = make_float2(v0, v1);
                float v2 = C2[2] + fr[mt][1][nt].x + BU[col];
                float v3 = C2[3] + fr[mt][1][nt].y + BU[col + 1];
                nb[mt] += v2 * v2 + v3 * v3;
                *(float2*)(out + (r0_ + 8) * ED + col) = make_float2(v2, v3);
            }
        }
    }

    // ---- cross-warp row sumsq: 4 dq-warps per row ----
    #pragma unroll
    for (int o = 1; o < 4; o <<= 1) {
        na[0] += __shfl_xor_sync(0xFFFFFFFFu, na[0], o);
        na[1] += __shfl_xor_sync(0xFFFFFFFFu, na[1], o);
        nb[0] += __shfl_xor_sync(0xFFFFFFFFu, nb[0], o);
        nb[1] += __shfl_xor_sync(0xFFFFFFFFu, nb[1], o);
    }
    if ((lane & 3) == 0) {
        float* NR = (float*)(sb + O_NRM);
        int rl = lane >> 2;
        NR[(md * 32 + rl) * 5 + dq]      = na[0];
        NR[(md * 32 + rl + 8) * 5 + dq]  = nb[0];
        NR[(md * 32 + 16 + rl) * 5 + dq] = na[1];
        NR[(md * 32 + 24 + rl) * 5 + dq] = nb[1];
    }
    __syncthreads();
    if (tid < MT) {
        const float* NR = (const float*)(sb + O_NRM) + tid * 5;
        float s = NR[0] + NR[1] + NR[2] + NR[3];
        ((float*)(sb + O_INV))[tid] = 1.f / fmaxf(sqrtf(s), 1e-12f);
    }
    __syncthreads();

    // ---- rescale (L2-hot re-read of this CTA's output) ----
    {
        float sc = ((float*)(sb + O_INV))[cr];
        float4* op = (float4*)(out + (row0 + cr) * ED);
        #pragma unroll 8
        for (int j = 0; j < 96; ++j) {
            float4 v = op[j * 4 + cs];
            v.x *= sc; v.y *= sc; v.z *= sc; v.w *= sc;
            op[j * 4 + cs] = v;
        }
    }
}

extern "C" void kernel_launch(void* const* d_in, const int* in_sizes, int n_in,
                              void* d_out, int out_size) {
    const float* x      = (const float*)d_in[0];
    const float* w_down = (const float*)d_in[1];
    const float* b_down = (const float*)d_in[2];
    const float* w_up   = (const float*)d_in[3];
    const float* b_up   = (const float*)d_in[4];
    const float* gamma  = (const float*)d_in[5];
    const float* beta   = (const float*)d_in[6];
    float* out = (float*)d_out;

    const int n_rows = in_sizes[0] / ED;   // 32768

    cudaFuncSetAttribute(peft_mma, cudaFuncAttributeMaxDynamicSharedMemorySize, SMEM_REQ);

    prep_all<<<88, 256>>>(w_down, b_down, gamma, beta, w_up);
    peft_mma<<<n_rows / MT, NTH, SMEM_REQ>>>(x, b_up, out);
}

// round 10
// speedup vs baseline: 1.4671x; 1.0571x over previous
#include <cuda_runtime.h>
#include <cuda_bf16.h>
#include <math.h>

#define ED 1536
#define BN 64
#define MT 64
#define NTH 256
#define NCH 24

// ---- smem byte offsets (from 1KB-aligned base) ----
#define O_XB(b)  ((b) * 16384)            // X chunk: hi @+0 (8KB), lo @+8192
#define O_WB(b)  (32768 + (b) * 8192)     // W chunk double buffer (bf16 hi only, 8KB)
#define O_HH     49152                    // H bf16: 64 rows x 128B
#define O_BU     57344
#define O_S1     63488
#define O_S2     63744
#define O_MS     64000
#define O_RS     64256
#define O_NRM    64512                    // 64 x 5 fp32
#define O_INV    65792
#define SMEM_REQ (66048 + 1024)

__device__ __nv_bfloat16 g_wdh[BN * ED];   // [24][64 n][64 k]  (gamma-folded, bf16)
__device__ __nv_bfloat16 g_wuh[ED * BN];   // [24][64 d][64 k]
__device__ float g_S1[BN], g_S2[BN];

// 128B rows, 8 units of 16B, XOR swizzle
__device__ __forceinline__ unsigned SWB(unsigned r, unsigned u) {
    return r * 128 + (((u ^ r) & 7) * 16);
}

__device__ __forceinline__ void ldsm4(unsigned* r, unsigned a) {
    asm volatile("ldmatrix.sync.aligned.m8n8.x4.shared.b16 {%0,%1,%2,%3}, [%4];"
                 : "=r"(r[0]), "=r"(r[1]), "=r"(r[2]), "=r"(r[3]) : "r"(a));
}
__device__ __forceinline__ void mma_bf(float* c, const unsigned* a, const unsigned* b) {
    asm volatile("mma.sync.aligned.m16n8k16.row.col.f32.bf16.bf16.f32 "
                 "{%0,%1,%2,%3},{%4,%5,%6,%7},{%8,%9},{%0,%1,%2,%3};"
                 : "+f"(c[0]), "+f"(c[1]), "+f"(c[2]), "+f"(c[3])
                 : "r"(a[0]), "r"(a[1]), "r"(a[2]), "r"(a[3]), "r"(b[0]), "r"(b[1]));
}
__device__ __forceinline__ void cp16(unsigned dst, const void* src) {
    asm volatile("cp.async.cg.shared.global [%0], [%1], 16;" :: "r"(dst), "l"(src));
}
#define CP_COMMIT() asm volatile("cp.async.commit_group;" ::: "memory")
#define CP_WAIT0()  asm volatile("cp.async.wait_group 0;" ::: "memory")

__device__ __forceinline__ void split2(float a, float b, unsigned& h, unsigned& l) {
    __nv_bfloat16 ha = __float2bfloat16_rn(a), hb = __float2bfloat16_rn(b);
    float ra = a - __bfloat162float(ha), rb = b - __bfloat162float(hb);
    __nv_bfloat16 la = __float2bfloat16_rn(ra), lb = __float2bfloat16_rn(rb);
    h = (unsigned)__bfloat16_as_ushort(ha) | ((unsigned)__bfloat16_as_ushort(hb) << 16);
    l = (unsigned)__bfloat16_as_ushort(la) | ((unsigned)__bfloat16_as_ushort(lb) << 16);
}
__device__ __forceinline__ unsigned pack_bf(float a, float b) {
    __nv_bfloat16 ha = __float2bfloat16_rn(a), hb = __float2bfloat16_rn(b);
    return (unsigned)__bfloat16_as_ushort(ha) | ((unsigned)__bfloat16_as_ushort(hb) << 16);
}
__device__ __forceinline__ float gelu_exact(float t) {
    return 0.5f * t * (1.f + erff(t * 0.70710678118654752f));
}

// ---------- merged prep: blocks 0..63 -> w_down row; 64..87 -> w_up chunk ----------
__global__ void prep_all(const float* __restrict__ w_down, const float* __restrict__ b_down,
                         const float* __restrict__ gamma,  const float* __restrict__ beta,
                         const float* __restrict__ w_up) {
    int tid = threadIdx.x;
    if (blockIdx.x < 64) {
        int b = blockIdx.x;
        float s1 = 0.f, s2 = 0.f;
        for (int k = tid; k < ED; k += 256) {
            float w = w_down[b * ED + k];
            float wg = w * gamma[k];
            __nv_bfloat16 hi = __float2bfloat16_rn(wg);
            s1 += __bfloat162float(hi);        // S1 matches the bf16 weights actually used
            s2 += beta[k] * w;
            int idx = (k >> 6) * 4096 + b * 64 + (k & 63);
            g_wdh[idx] = hi;
        }
        __shared__ float r1[256], r2[256];
        r1[tid] = s1; r2[tid] = s2; __syncthreads();
        for (int s = 128; s > 0; s >>= 1) {
            if (tid < s) { r1[tid] += r1[tid + s]; r2[tid] += r2[tid + s]; }
            __syncthreads();
        }
        if (tid == 0) { g_S1[b] = r1[0]; g_S2[b] = r2[0] + b_down[b]; }
    } else {
        int c = blockIdx.x - 64;
        for (int i = tid; i < 4096; i += 256) {
            int d = i >> 6, k = i & 63;
            g_wuh[c * 4096 + i] = __float2bfloat16_rn(w_up[(c * 64 + d) * BN + k]);
        }
    }
}

// ---------- main ----------
__global__ void __launch_bounds__(NTH, 2)
peft_mma(const float* __restrict__ x, const float* __restrict__ bup, float* __restrict__ out) {
    extern __shared__ char smraw[];
    unsigned rawa = (unsigned)__cvta_generic_to_shared(smraw);
    unsigned sa = (rawa + 1023) & ~1023u;
    char* sb = smraw + (sa - rawa);

    const int tid = threadIdx.x, warp = tid >> 5, lane = tid & 31;
    const int m = warp & 3, nh = warp >> 2;   // GEMM1: 4 m-tiles x 2 n-halves
    const long row0 = (long)blockIdx.x * MT;
    const int cr = tid >> 2, cs = tid & 3;    // conversion row / quarter
    const int cb = (lane & 3) * 2;            // col pair base

    float* BU  = (float*)(sb + O_BU);
    float* S1s = (float*)(sb + O_S1);
    float* S2s = (float*)(sb + O_S2);
    float* MSs = (float*)(sb + O_MS);
    float* RSs = (float*)(sb + O_RS);

    for (int i = tid; i < ED; i += NTH) BU[i] = bup[i];
    if (tid < BN) { S1s[tid] = g_S1[tid]; S2s[tid] = g_S2[tid]; }

    float sum = 0.f, sq = 0.f;

    // ---- prologue: stage Wd chunk 0 (hi only) + convert X chunk 0 ----
    {
        #pragma unroll
        for (int s = 0; s < 2; ++s) {
            int i = tid * 2 + s, n = i >> 3, u = i & 7;
            cp16(sa + O_WB(0) + SWB(n, u), g_wdh + n * 64 + u * 8);
        }
        CP_COMMIT();
    }
    {
        const float* xp = x + (row0 + cr) * ED;
        char* xb = sb + O_XB(0);
        #pragma unroll
        for (int g = 0; g < 2; ++g) {
            float4 v0 = *(const float4*)(xp + cs * 16 + g * 8);
            float4 v1 = *(const float4*)(xp + cs * 16 + g * 8 + 4);
            sum += v0.x + v0.y + v0.z + v0.w + v1.x + v1.y + v1.z + v1.w;
            sq  += v0.x*v0.x + v0.y*v0.y + v0.z*v0.z + v0.w*v0.w
                 + v1.x*v1.x + v1.y*v1.y + v1.z*v1.z + v1.w*v1.w;
            unsigned h0,l0,h1,l1,h2,l2,h3,l3;
            split2(v0.x, v0.y, h0, l0); split2(v0.z, v0.w, h1, l1);
            split2(v1.x, v1.y, h2, l2); split2(v1.z, v1.w, h3, l3);
            unsigned off = SWB(cr, 2 * cs + g);
            *(uint4*)(xb + off)        = make_uint4(h0, h1, h2, h3);
            *(uint4*)(xb + 8192 + off) = make_uint4(l0, l1, l2, l3);
        }
    }

    // ================= GEMM1: H[64,64] = X * (gamma*Wd)^T (2-term: (xh+xl)*wh) =================
    float C1[4][4];
    #pragma unroll
    for (int nt = 0; nt < 4; ++nt)
        #pragma unroll
        for (int i = 0; i < 4; ++i) C1[nt][i] = 0.f;

    float4 pf0, pf1, pf2, pf3;
    for (int c = 0; c < NCH; ++c) {
        CP_WAIT0();
        __syncthreads();
        if (c < NCH - 1) {
            #pragma unroll
            for (int s = 0; s < 2; ++s) {
                int i = tid * 2 + s, n = i >> 3, u = i & 7;
                cp16(sa + O_WB((c + 1) & 1) + SWB(n, u), g_wdh + (c + 1) * 4096 + n * 64 + u * 8);
            }
            CP_COMMIT();
            const float* xp = x + (row0 + cr) * ED + (c + 1) * 64 + cs * 16;
            pf0 = *(const float4*)(xp);
            pf1 = *(const float4*)(xp + 4);
            pf2 = *(const float4*)(xp + 8);
            pf3 = *(const float4*)(xp + 12);
        }
        unsigned xb = sa + O_XB(c & 1);
        unsigned wb = sa + O_WB(c & 1);
        const unsigned rowA = m * 16 + (lane & 15);
        #pragma unroll
        for (int kp = 0; kp < 2; ++kp) {
            unsigned ah0[4], al0[4], ah1[4], al1[4];
            unsigned uA0 = 4 * kp + (lane >> 4), uA1 = uA0 + 2;
            ldsm4(ah0, xb + SWB(rowA, uA0));
            ldsm4(al0, xb + 8192 + SWB(rowA, uA0));
            ldsm4(ah1, xb + SWB(rowA, uA1));
            ldsm4(al1, xb + 8192 + SWB(rowA, uA1));
            #pragma unroll
            for (int nt = 0; nt < 4; ++nt) {
                unsigned bh[4];
                unsigned rowB = nh * 32 + nt * 8 + (lane & 7);
                unsigned uB = 4 * kp + (lane >> 3);
                ldsm4(bh, wb + SWB(rowB, uB));
                float* Cp = C1[nt];
                mma_bf(Cp, ah0, bh);     mma_bf(Cp, al0, bh);
                mma_bf(Cp, ah1, bh + 2); mma_bf(Cp, al1, bh + 2);
            }
        }
        if (c < NCH - 1) {
            char* xcb = sb + O_XB((c + 1) & 1);
            float4 vv[4] = {pf0, pf1, pf2, pf3};
            #pragma unroll
            for (int g = 0; g < 2; ++g) {
                float4 v0 = vv[g * 2], v1 = vv[g * 2 + 1];
                sum += v0.x + v0.y + v0.z + v0.w + v1.x + v1.y + v1.z + v1.w;
                sq  += v0.x*v0.x + v0.y*v0.y + v0.z*v0.z + v0.w*v0.w
                     + v1.x*v1.x + v1.y*v1.y + v1.z*v1.z + v1.w*v1.w;
                unsigned h0,l0,h1,l1,h2,l2,h3,l3;
                split2(v0.x, v0.y, h0, l0); split2(v0.z, v0.w, h1, l1);
                split2(v1.x, v1.y, h2, l2); split2(v1.z, v1.w, h3, l3);
                unsigned off = SWB(cr, 2 * cs + g);
                *(uint4*)(xcb + off)        = make_uint4(h0, h1, h2, h3);
                *(uint4*)(xcb + 8192 + off) = make_uint4(l0, l1, l2, l3);
            }
        }
    }

    // ---- LN stats: 4 lanes per row -> MS/RS ----
    #pragma unroll
    for (int o = 1; o < 4; o <<= 1) {
        sum += __shfl_xor_sync(0xFFFFFFFFu, sum, o);
        sq  += __shfl_xor_sync(0xFFFFFFFFu, sq,  o);
    }
    if (cs == 0) {
        float mean = sum * (1.f / ED);
        MSs[cr] = mean;
        RSs[cr] = rsqrtf(sq * (1.f / ED) - mean * mean + 1e-5f);
    }
    __syncthreads();

    // ---- LN finalize + GELU directly on C1 frags -> HH (bf16) ----
    {
        int rA_ = m * 16 + (lane >> 2), rB_ = rA_ + 8;
        float meanA = MSs[rA_], rstdA = RSs[rA_];
        float meanB = MSs[rB_], rstdB = RSs[rB_];
        #pragma unroll
        for (int nt = 0; nt < 4; ++nt) {
            int c0 = nh * 32 + nt * 8 + cb;
            float2 s1p = *(const float2*)(S1s + c0);
            float2 s2p = *(const float2*)(S2s + c0);
            float tA0 = rstdA * C1[nt][0] - rstdA * meanA * s1p.x + s2p.x;
            float tA1 = rstdA * C1[nt][1] - rstdA * meanA * s1p.y + s2p.y;
            float tB0 = rstdB * C1[nt][2] - rstdB * meanB * s1p.x + s2p.x;
            float tB1 = rstdB * C1[nt][3] - rstdB * meanB * s1p.y + s2p.y;
            unsigned u = nh * 4 + nt;
            *(unsigned*)(sb + O_HH + SWB(rA_, u) + cb * 2) = pack_bf(gelu_exact(tA0), gelu_exact(tA1));
            *(unsigned*)(sb + O_HH + SWB(rB_, u) + cb * 2) = pack_bf(gelu_exact(tB0), gelu_exact(tB1));
        }
    }
    __syncthreads();

    // ================= GEMM2 (single-term bf16): out = H * Wu^T + b_up + x =================
    // warp grid: 2 m-halves (32 rows) x 4 d-quarters (16 cols per 64-chunk)
    const int md = warp & 1;
    const int dq = warp >> 1;
    unsigned Ah[2][4][4];
    {
        #pragma unroll
        for (int mt = 0; mt < 2; ++mt) {
            unsigned rowA_ = md * 32 + mt * 16 + (lane & 15);
            #pragma unroll
            for (int kk = 0; kk < 4; ++kk) {
                unsigned uA = 2 * kk + (lane >> 4);
                ldsm4(Ah[mt][kk], sa + O_HH + SWB(rowA_, uA));
            }
        }
    }
    {
        #pragma unroll
        for (int s = 0; s < 2; ++s) {
            int i = tid * 2 + s, d = i >> 3, u = i & 7;
            cp16(sa + O_WB(0) + SWB(d, u), g_wuh + d * 64 + u * 8);
        }
        CP_COMMIT();
    }

    const long rA0 = row0 + md * 32 + (lane >> 2);       // mt=0 rows
    const long rA1 = rA0 + 16;                            // mt=1 rows
    float na[2] = {0.f, 0.f}, nb[2] = {0.f, 0.f};
    for (int c = 0; c < NCH; ++c) {
        CP_WAIT0();
        __syncthreads();
        if (c < NCH - 1) {
            #pragma unroll
            for (int s = 0; s < 2; ++s) {
                int i = tid * 2 + s, d = i >> 3, u = i & 7;
                cp16(sa + O_WB((c + 1) & 1) + SWB(d, u), g_wuh + (c + 1) * 4096 + d * 64 + u * 8);
            }
            CP_COMMIT();
        }
        // residual prefetch: [mt][half][nt]
        float2 fr[2][2][2];
        #pragma unroll
        for (int nt = 0; nt < 2; ++nt) {
            int col = c * 64 + dq * 16 + nt * 8 + cb;
            fr[0][0][nt] = *(const float2*)(x + rA0 * ED + col);
            fr[0][1][nt] = *(const float2*)(x + (rA0 + 8) * ED + col);
            fr[1][0][nt] = *(const float2*)(x + rA1 * ED + col);
            fr[1][1][nt] = *(const float2*)(x + (rA1 + 8) * ED + col);
        }
        unsigned wb = sa + O_WB(c & 1);
        unsigned bh[2][4];
        #pragma unroll
        for (int nt = 0; nt < 2; ++nt) {
            unsigned rowB_ = dq * 16 + nt * 8 + (lane & 7);
            #pragma unroll
            for (int kp = 0; kp < 2; ++kp) {
                unsigned uB = 4 * kp + (lane >> 3);
                ldsm4(bh[kp], wb + SWB(rowB_, uB));
            }
            #pragma unroll
            for (int mt = 0; mt < 2; ++mt) {
                float C2[4] = {0.f, 0.f, 0.f, 0.f};
                #pragma unroll
                for (int kk = 0; kk < 4; ++kk)
                    mma_bf(C2, Ah[mt][kk], &bh[kk >> 1][(kk & 1) * 2]);
                int col = c * 64 + dq * 16 + nt * 8 + cb;
                long r0_ = (mt ? rA1 : rA0);
                float v0 = C2[0] + fr[mt][0][nt].x + BU[col];
                float v1 = C2[1] + fr[mt][0][nt].y + BU[col + 1];
                na[mt] += v0 * v0 + v1 * v1;
                *(float2*)(out + r0_ * ED + col) = make_float2(v0, v1);
                float v2 = C2[2] + fr[mt][1][nt].x + BU[col];
                float v3 = C2[3] + fr[mt][1][nt].y + BU[col + 1];
                nb[mt] += v2 * v2 + v3 * v3;
                *(float2*)(out + (r0_ + 8) * ED + col) = make_float2(v2, v3);
            }
        }
    }

    // ---- cross-warp row sumsq: 4 dq-warps per row ----
    #pragma unroll
    for (int o = 1; o < 4; o <<= 1) {
        na[0] += __shfl_xor_sync(0xFFFFFFFFu, na[0], o);
        na[1] += __shfl_xor_sync(0xFFFFFFFFu, na[1], o);
        nb[0] += __shfl_xor_sync(0xFFFFFFFFu, nb[0], o);
        nb[1] += __shfl_xor_sync(0xFFFFFFFFu, nb[1], o);
    }
    if ((lane & 3) == 0) {
        float* NR = (float*)(sb + O_NRM);
        int rl = lane >> 2;
        NR[(md * 32 + rl) * 5 + dq]      = na[0];
        NR[(md * 32 + rl + 8) * 5 + dq]  = nb[0];
        NR[(md * 32 + 16 + rl) * 5 + dq] = na[1];
        NR[(md * 32 + 24 + rl) * 5 + dq] = nb[1];
    }
    __syncthreads();
    if (tid < MT) {
        const float* NR = (const float*)(sb + O_NRM) + tid * 5;
        float s = NR[0] + NR[1] + NR[2] + NR[3];
        ((float*)(sb + O_INV))[tid] = 1.f / fmaxf(sqrtf(s), 1e-12f);
    }
    __syncthreads();

    // ---- rescale (L2-hot re-read of this CTA's output) ----
    {
        float sc = ((float*)(sb + O_INV))[cr];
        float4* op = (float4*)(out + (row0 + cr) * ED);
        #pragma unroll 8
        for (int j = 0; j < 96; ++j) {
            float4 v = op[j * 4 + cs];
            v.x *= sc; v.y *= sc; v.z *= sc; v.w *= sc;
            op[j * 4 + cs] = v;
        }
    }
}

extern "C" void kernel_launch(void* const* d_in, const int* in_sizes, int n_in,
                              void* d_out, int out_size) {
    const float* x      = (const float*)d_in[0];
    const float* w_down = (const float*)d_in[1];
    const float* b_down = (const float*)d_in[2];
    const float* w_up   = (const float*)d_in[3];
    const float* b_up   = (const float*)d_in[4];
    const float* gamma  = (const float*)d_in[5];
    const float* beta   = (const float*)d_in[6];
    float* out = (float*)d_out;

    const int n_rows = in_sizes[0] / ED;   // 32768

    cudaFuncSetAttribute(peft_mma, cudaFuncAttributeMaxDynamicSharedMemorySize, SMEM_REQ);

    prep_all<<<88, 256>>>(w_down, b_down, gamma, beta, w_up);
    peft_mma<<<n_rows / MT, NTH, SMEM_REQ>>>(x, b_up, out);
}

// round 11
// speedup vs baseline: 1.5250x; 1.0395x over previous
#include <cuda_runtime.h>
#include <cuda_bf16.h>
#include <math.h>

#define ED 1536
#define BN 64
#define MT 64
#define NTH 256
#define NCH 24

// ---- smem byte offsets (from 1KB-aligned base) ----
#define O_XB(b)  ((b) * 8192)             // X chunk bf16 hi, double buffer
#define O_WB(b)  (16384 + (b) * 8192)     // W chunk bf16, double buffer
#define O_HH     32768                    // H bf16: 64 rows x 128B
#define O_BU     40960
#define O_S1     47104
#define O_S2     47360
#define O_MS     47616
#define O_RS     47872
#define O_NRM    48128                    // 64 x 5 fp32
#define O_INV    49408
#define SMEM_REQ (49664 + 1024)

__device__ __nv_bfloat16 g_wdh[BN * ED];   // [24][64 n][64 k]  (gamma-folded, bf16)
__device__ __nv_bfloat16 g_wuh[ED * BN];   // [24][64 d][64 k]
__device__ float g_S1[BN], g_S2[BN];

// 128B rows, 8 units of 16B, XOR swizzle
__device__ __forceinline__ unsigned SWB(unsigned r, unsigned u) {
    return r * 128 + (((u ^ r) & 7) * 16);
}

__device__ __forceinline__ void ldsm4(unsigned* r, unsigned a) {
    asm volatile("ldmatrix.sync.aligned.m8n8.x4.shared.b16 {%0,%1,%2,%3}, [%4];"
                 : "=r"(r[0]), "=r"(r[1]), "=r"(r[2]), "=r"(r[3]) : "r"(a));
}
__device__ __forceinline__ void mma_bf(float* c, const unsigned* a, const unsigned* b) {
    asm volatile("mma.sync.aligned.m16n8k16.row.col.f32.bf16.bf16.f32 "
                 "{%0,%1,%2,%3},{%4,%5,%6,%7},{%8,%9},{%0,%1,%2,%3};"
                 : "+f"(c[0]), "+f"(c[1]), "+f"(c[2]), "+f"(c[3])
                 : "r"(a[0]), "r"(a[1]), "r"(a[2]), "r"(a[3]), "r"(b[0]), "r"(b[1]));
}
__device__ __forceinline__ void cp16(unsigned dst, const void* src) {
    asm volatile("cp.async.cg.shared.global [%0], [%1], 16;" :: "r"(dst), "l"(src));
}
#define CP_COMMIT() asm volatile("cp.async.commit_group;" ::: "memory")
#define CP_WAIT0()  asm volatile("cp.async.wait_group 0;" ::: "memory")

__device__ __forceinline__ unsigned pack_bf(float a, float b) {
    __nv_bfloat16 ha = __float2bfloat16_rn(a), hb = __float2bfloat16_rn(b);
    return (unsigned)__bfloat16_as_ushort(ha) | ((unsigned)__bfloat16_as_ushort(hb) << 16);
}
__device__ __forceinline__ float gelu_exact(float t) {
    return 0.5f * t * (1.f + erff(t * 0.70710678118654752f));
}

// ---------- merged prep: blocks 0..63 -> w_down row; 64..87 -> w_up chunk ----------
__global__ void prep_all(const float* __restrict__ w_down, const float* __restrict__ b_down,
                         const float* __restrict__ gamma,  const float* __restrict__ beta,
                         const float* __restrict__ w_up) {
    int tid = threadIdx.x;
    if (blockIdx.x < 64) {
        int b = blockIdx.x;
        float s1 = 0.f, s2 = 0.f;
        for (int k = tid; k < ED; k += 256) {
            float w = w_down[b * ED + k];
            float wg = w * gamma[k];
            __nv_bfloat16 hi = __float2bfloat16_rn(wg);
            s1 += __bfloat162float(hi);        // S1 matches the bf16 weights actually used
            s2 += beta[k] * w;
            int idx = (k >> 6) * 4096 + b * 64 + (k & 63);
            g_wdh[idx] = hi;
        }
        __shared__ float r1[256], r2[256];
        r1[tid] = s1; r2[tid] = s2; __syncthreads();
        for (int s = 128; s > 0; s >>= 1) {
            if (tid < s) { r1[tid] += r1[tid + s]; r2[tid] += r2[tid + s]; }
            __syncthreads();
        }
        if (tid == 0) { g_S1[b] = r1[0]; g_S2[b] = r2[0] + b_down[b]; }
    } else {
        int c = blockIdx.x - 64;
        for (int i = tid; i < 4096; i += 256) {
            int d = i >> 6, k = i & 63;
            g_wuh[c * 4096 + i] = __float2bfloat16_rn(w_up[(c * 64 + d) * BN + k]);
        }
    }
}

// ---------- main ----------
__global__ void __launch_bounds__(NTH, 2)
peft_mma(const float* __restrict__ x, const float* __restrict__ bup, float* __restrict__ out) {
    extern __shared__ char smraw[];
    unsigned rawa = (unsigned)__cvta_generic_to_shared(smraw);
    unsigned sa = (rawa + 1023) & ~1023u;
    char* sb = smraw + (sa - rawa);

    const int tid = threadIdx.x, warp = tid >> 5, lane = tid & 31;
    const int m = warp & 3, nh = warp >> 2;   // GEMM1: 4 m-tiles x 2 n-halves
    const long row0 = (long)blockIdx.x * MT;
    const int cr = tid >> 2, cs = tid & 3;    // conversion row / quarter
    const int cb = (lane & 3) * 2;            // col pair base

    float* BU  = (float*)(sb + O_BU);
    float* S1s = (float*)(sb + O_S1);
    float* S2s = (float*)(sb + O_S2);
    float* MSs = (float*)(sb + O_MS);
    float* RSs = (float*)(sb + O_RS);

    for (int i = tid; i < ED; i += NTH) BU[i] = bup[i];
    if (tid < BN) { S1s[tid] = g_S1[tid]; S2s[tid] = g_S2[tid]; }

    float sum = 0.f, sq = 0.f;

    // ---- prologue: stage Wd chunk 0 + convert X chunk 0 (bf16 hi) ----
    {
        #pragma unroll
        for (int s = 0; s < 2; ++s) {
            int i = tid * 2 + s, n = i >> 3, u = i & 7;
            cp16(sa + O_WB(0) + SWB(n, u), g_wdh + n * 64 + u * 8);
        }
        CP_COMMIT();
    }
    {
        const float* xp = x + (row0 + cr) * ED;
        char* xb = sb + O_XB(0);
        #pragma unroll
        for (int g = 0; g < 2; ++g) {
            float4 v0 = *(const float4*)(xp + cs * 16 + g * 8);
            float4 v1 = *(const float4*)(xp + cs * 16 + g * 8 + 4);
            sum += v0.x + v0.y + v0.z + v0.w + v1.x + v1.y + v1.z + v1.w;
            sq  += v0.x*v0.x + v0.y*v0.y + v0.z*v0.z + v0.w*v0.w
                 + v1.x*v1.x + v1.y*v1.y + v1.z*v1.z + v1.w*v1.w;
            unsigned off = SWB(cr, 2 * cs + g);
            *(uint4*)(xb + off) = make_uint4(pack_bf(v0.x, v0.y), pack_bf(v0.z, v0.w),
                                             pack_bf(v1.x, v1.y), pack_bf(v1.z, v1.w));
        }
    }

    // ================= GEMM1: H[64,64] = X * (gamma*Wd)^T (bf16 single-term) =================
    float C1[4][4];
    #pragma unroll
    for (int nt = 0; nt < 4; ++nt)
        #pragma unroll
        for (int i = 0; i < 4; ++i) C1[nt][i] = 0.f;

    float4 pf0, pf1, pf2, pf3;
    for (int c = 0; c < NCH; ++c) {
        CP_WAIT0();
        __syncthreads();
        if (c < NCH - 1) {
            #pragma unroll
            for (int s = 0; s < 2; ++s) {
                int i = tid * 2 + s, n = i >> 3, u = i & 7;
                cp16(sa + O_WB((c + 1) & 1) + SWB(n, u), g_wdh + (c + 1) * 4096 + n * 64 + u * 8);
            }
            CP_COMMIT();
            const float* xp = x + (row0 + cr) * ED + (c + 1) * 64 + cs * 16;
            pf0 = *(const float4*)(xp);
            pf1 = *(const float4*)(xp + 4);
            pf2 = *(const float4*)(xp + 8);
            pf3 = *(const float4*)(xp + 12);
        }
        unsigned xb = sa + O_XB(c & 1);
        unsigned wb = sa + O_WB(c & 1);
        const unsigned rowA = m * 16 + (lane & 15);
        #pragma unroll
        for (int kp = 0; kp < 2; ++kp) {
            unsigned ah0[4], ah1[4];
            unsigned uA0 = 4 * kp + (lane >> 4), uA1 = uA0 + 2;
            ldsm4(ah0, xb + SWB(rowA, uA0));
            ldsm4(ah1, xb + SWB(rowA, uA1));
            #pragma unroll
            for (int nt = 0; nt < 4; ++nt) {
                unsigned bh[4];
                unsigned rowB = nh * 32 + nt * 8 + (lane & 7);
                unsigned uB = 4 * kp + (lane >> 3);
                ldsm4(bh, wb + SWB(rowB, uB));
                mma_bf(C1[nt], ah0, bh);
                mma_bf(C1[nt], ah1, bh + 2);
            }
        }
        if (c < NCH - 1) {
            char* xcb = sb + O_XB((c + 1) & 1);
            float4 vv[4] = {pf0, pf1, pf2, pf3};
            #pragma unroll
            for (int g = 0; g < 2; ++g) {
                float4 v0 = vv[g * 2], v1 = vv[g * 2 + 1];
                sum += v0.x + v0.y + v0.z + v0.w + v1.x + v1.y + v1.z + v1.w;
                sq  += v0.x*v0.x + v0.y*v0.y + v0.z*v0.z + v0.w*v0.w
                     + v1.x*v1.x + v1.y*v1.y + v1.z*v1.z + v1.w*v1.w;
                unsigned off = SWB(cr, 2 * cs + g);
                *(uint4*)(xcb + off) = make_uint4(pack_bf(v0.x, v0.y), pack_bf(v0.z, v0.w),
                                                  pack_bf(v1.x, v1.y), pack_bf(v1.z, v1.w));
            }
        }
    }

    // ---- LN stats: 4 lanes per row -> MS/RS ----
    #pragma unroll
    for (int o = 1; o < 4; o <<= 1) {
        sum += __shfl_xor_sync(0xFFFFFFFFu, sum, o);
        sq  += __shfl_xor_sync(0xFFFFFFFFu, sq,  o);
    }
    if (cs == 0) {
        float mean = sum * (1.f / ED);
        MSs[cr] = mean;
        RSs[cr] = rsqrtf(sq * (1.f / ED) - mean * mean + 1e-5f);
    }
    __syncthreads();

    // ---- LN finalize + GELU directly on C1 frags -> HH (bf16) ----
    {
        int rA_ = m * 16 + (lane >> 2), rB_ = rA_ + 8;
        float meanA = MSs[rA_], rstdA = RSs[rA_];
        float meanB = MSs[rB_], rstdB = RSs[rB_];
        #pragma unroll
        for (int nt = 0; nt < 4; ++nt) {
            int c0 = nh * 32 + nt * 8 + cb;
            float2 s1p = *(const float2*)(S1s + c0);
            float2 s2p = *(const float2*)(S2s + c0);
            float tA0 = rstdA * C1[nt][0] - rstdA * meanA * s1p.x + s2p.x;
            float tA1 = rstdA * C1[nt][1] - rstdA * meanA * s1p.y + s2p.y;
            float tB0 = rstdB * C1[nt][2] - rstdB * meanB * s1p.x + s2p.x;
            float tB1 = rstdB * C1[nt][3] - rstdB * meanB * s1p.y + s2p.y;
            unsigned u = nh * 4 + nt;
            *(unsigned*)(sb + O_HH + SWB(rA_, u) + cb * 2) = pack_bf(gelu_exact(tA0), gelu_exact(tA1));
            *(unsigned*)(sb + O_HH + SWB(rB_, u) + cb * 2) = pack_bf(gelu_exact(tB0), gelu_exact(tB1));
        }
    }
    __syncthreads();

    // ================= GEMM2 (single-term bf16): out = H * Wu^T + b_up + x =================
    // warp grid: 2 m-halves (32 rows) x 4 d-quarters (16 cols per 64-chunk)
    const int md = warp & 1;
    const int dq = warp >> 1;
    unsigned Ah[2][4][4];
    {
        #pragma unroll
        for (int mt = 0; mt < 2; ++mt) {
            unsigned rowA_ = md * 32 + mt * 16 + (lane & 15);
            #pragma unroll
            for (int kk = 0; kk < 4; ++kk) {
                unsigned uA = 2 * kk + (lane >> 4);
                ldsm4(Ah[mt][kk], sa + O_HH + SWB(rowA_, uA));
            }
        }
    }
    {
        #pragma unroll
        for (int s = 0; s < 2; ++s) {
            int i = tid * 2 + s, d = i >> 3, u = i & 7;
            cp16(sa + O_WB(0) + SWB(d, u), g_wuh + d * 64 + u * 8);
        }
        CP_COMMIT();
    }

    const long rA0 = row0 + md * 32 + (lane >> 2);       // mt=0 rows
    const long rA1 = rA0 + 16;                            // mt=1 rows
    float na[2] = {0.f, 0.f}, nb[2] = {0.f, 0.f};
    for (int c = 0; c < NCH; ++c) {
        CP_WAIT0();
        __syncthreads();
        if (c < NCH - 1) {
            #pragma unroll
            for (int s = 0; s < 2; ++s) {
                int i = tid * 2 + s, d = i >> 3, u = i & 7;
                cp16(sa + O_WB((c + 1) & 1) + SWB(d, u), g_wuh + (c + 1) * 4096 + d * 64 + u * 8);
            }
            CP_COMMIT();
        }
        // residual prefetch: [mt][half][nt]
        float2 fr[2][2][2];
        #pragma unroll
        for (int nt = 0; nt < 2; ++nt) {
            int col = c * 64 + dq * 16 + nt * 8 + cb;
            fr[0][0][nt] = *(const float2*)(x + rA0 * ED + col);
            fr[0][1][nt] = *(const float2*)(x + (rA0 + 8) * ED + col);
            fr[1][0][nt] = *(const float2*)(x + rA1 * ED + col);
            fr[1][1][nt] = *(const float2*)(x + (rA1 + 8) * ED + col);
        }
        unsigned wb = sa + O_WB(c & 1);
        unsigned bh[2][4];
        #pragma unroll
        for (int nt = 0; nt < 2; ++nt) {
            unsigned rowB_ = dq * 16 + nt * 8 + (lane & 7);
            #pragma unroll
            for (int kp = 0; kp < 2; ++kp) {
                unsigned uB = 4 * kp + (lane >> 3);
                ldsm4(bh[kp], wb + SWB(rowB_, uB));
            }
            #pragma unroll
            for (int mt = 0; mt < 2; ++mt) {
                float C2[4] = {0.f, 0.f, 0.f, 0.f};
                #pragma unroll
                for (int kk = 0; kk < 4; ++kk)
                    mma_bf(C2, Ah[mt][kk], &bh[kk >> 1][(kk & 1) * 2]);
                int col = c * 64 + dq * 16 + nt * 8 + cb;
                long r0_ = (mt ? rA1 : rA0);
                float v0 = C2[0] + fr[mt][0][nt].x + BU[col];
                float v1 = C2[1] + fr[mt][0][nt].y + BU[col + 1];
                na[mt] += v0 * v0 + v1 * v1;
                *(float2*)(out + r0_ * ED + col) = make_float2(v0, v1);
                float v2 = C2[2] + fr[mt][1][nt].x + BU[col];
                float v3 = C2[3] + fr[mt][1][nt].y + BU[col + 1];
                nb[mt] += v2 * v2 + v3 * v3;
                *(float2*)(out + (r0_ + 8) * ED + col) = make_float2(v2, v3);
            }
        }
    }

    // ---- cross-warp row sumsq: 4 dq-warps per row ----
    #pragma unroll
    for (int o = 1; o < 4; o <<= 1) {
        na[0] += __shfl_xor_sync(0xFFFFFFFFu, na[0], o);
        na[1] += __shfl_xor_sync(0xFFFFFFFFu, na[1], o);
        nb[0] += __shfl_xor_sync(0xFFFFFFFFu, nb[0], o);
        nb[1] += __shfl_xor_sync(0xFFFFFFFFu, nb[1], o);
    }
    if ((lane & 3) == 0) {
        float* NR = (float*)(sb + O_NRM);
        int rl = lane >> 2;
        NR[(md * 32 + rl) * 5 + dq]      = na[0];
        NR[(md * 32 + rl + 8) * 5 + dq]  = nb[0];
        NR[(md * 32 + 16 + rl) * 5 + dq] = na[1];
        NR[(md * 32 + 24 + rl) * 5 + dq] = nb[1];
    }
    __syncthreads();
    if (tid < MT) {
        const float* NR = (const float*)(sb + O_NRM) + tid * 5;
        float s = NR[0] + NR[1] + NR[2] + NR[3];
        ((float*)(sb + O_INV))[tid] = 1.f / fmaxf(sqrtf(s), 1e-12f);
    }
    __syncthreads();

    // ---- rescale (L2-hot re-read of this CTA's output) ----
    {
        float sc = ((float*)(sb + O_INV))[cr];
        float4* op = (float4*)(out + (row0 + cr) * ED);
        #pragma unroll 8
        for (int j = 0; j < 96; ++j) {
            float4 v = op[j * 4 + cs];
            v.x *= sc; v.y *= sc; v.z *= sc; v.w *= sc;
            op[j * 4 + cs] = v;
        }
    }
}

extern "C" void kernel_launch(void* const* d_in, const int* in_sizes, int n_in,
                              void* d_out, int out_size) {
    const float* x      = (const float*)d_in[0];
    const float* w_down = (const float*)d_in[1];
    const float* b_down = (const float*)d_in[2];
    const float* w_up   = (const float*)d_in[3];
    const float* b_up   = (const float*)d_in[4];
    const float* gamma  = (const float*)d_in[5];
    const float* beta   = (const float*)d_in[6];
    float* out = (float*)d_out;

    const int n_rows = in_sizes[0] / ED;   // 32768

    cudaFuncSetAttribute(peft_mma, cudaFuncAttributeMaxDynamicSharedMemorySize, SMEM_REQ);

    prep_all<<<88, 256>>>(w_down, b_down, gamma, beta, w_up);
    peft_mma<<<n_rows / MT, NTH, SMEM_REQ>>>(x, b_up, out);
}